// round 12
// baseline (speedup 1.0000x reference)
#include <cuda_runtime.h>
#include <cuda_bf16.h>
#include <math.h>
#include <stdint.h>

// ---------------- problem constants ----------------
#define BSZ     4
#define SEQL    2048
#define DMODEL  1024
#define DINNER  2048
#define DHALF   1024
#define DSTATE  16
#define DTRANK  64
#define MROWS   (BSZ * SEQL)            // 8192
#define XDBL_N  (DTRANK + 2 * DSTATE)   // 96
#define TC      64                      // scan chunk length
#define NCH     (SEQL / TC)             // 32 chunks

// ---------------- scratch (device globals; no allocation allowed) ----------------
__device__ __align__(16) float g_xz   [MROWS * DINNER];
__device__ __align__(16) float g_xc   [MROWS * DHALF];
__device__ __align__(16) float g_xdbl [MROWS * XDBL_N];
__device__ __align__(16) float g_delta[MROWS * DHALF];
__device__ __align__(16) float g_S    [BSZ * NCH * DHALF];
__device__ __align__(16) float g_H    [BSZ * NCH * DHALF * DSTATE];

// bf16 split operands for tensor-core GEMMs
__device__ __align__(16) __nv_bfloat16 g_xhi   [MROWS * DMODEL];
__device__ __align__(16) __nv_bfloat16 g_xlo   [MROWS * DMODEL];
__device__ __align__(16) __nv_bfloat16 g_chi   [MROWS * DINNER];   // [y | z] hi
__device__ __align__(16) __nv_bfloat16 g_clo   [MROWS * DINNER];   // [y | z] lo
__device__ __align__(16) __nv_bfloat16 g_binhi [DINNER * DMODEL];  // W_in^T  [2048][1024]
__device__ __align__(16) __nv_bfloat16 g_binlo [DINNER * DMODEL];
__device__ __align__(16) __nv_bfloat16 g_bouthi[DMODEL * DINNER];  // W_out^T [1024][2048]
__device__ __align__(16) __nv_bfloat16 g_boutlo[DMODEL * DINNER];

// ---------------- PTX helpers (sm_80-class: cp.async / ldmatrix / mma.sync) ----------------
__device__ __forceinline__ uint32_t smem_u32(const void* p) {
    uint32_t a;
    asm("{ .reg .u64 t; cvta.to.shared.u64 t, %1; cvt.u32.u64 %0, t; }" : "=r"(a) : "l"(p));
    return a;
}
__device__ __forceinline__ void cp_async16(uint32_t dst, const void* src) {
    asm volatile("cp.async.cg.shared.global [%0], [%1], 16;" :: "r"(dst), "l"(src));
}
#define CP_COMMIT() asm volatile("cp.async.commit_group;" ::: "memory")
#define CP_WAIT1()  asm volatile("cp.async.wait_group 1;" ::: "memory")
#define CP_WAIT0()  asm volatile("cp.async.wait_group 0;" ::: "memory")

__device__ __forceinline__ void ldsm4(uint32_t (&r)[4], uint32_t addr) {
    asm volatile("ldmatrix.sync.aligned.m8n8.x4.shared.b16 {%0,%1,%2,%3}, [%4];"
        : "=r"(r[0]), "=r"(r[1]), "=r"(r[2]), "=r"(r[3]) : "r"(addr));
}
__device__ __forceinline__ void mma16816(float (&c)[4], const uint32_t (&a)[4],
                                         uint32_t b0, uint32_t b1) {
    asm volatile("mma.sync.aligned.m16n8k16.row.col.f32.bf16.bf16.f32 "
        "{%0,%1,%2,%3}, {%4,%5,%6,%7}, {%8,%9}, {%0,%1,%2,%3};"
        : "+f"(c[0]), "+f"(c[1]), "+f"(c[2]), "+f"(c[3])
        : "r"(a[0]), "r"(a[1]), "r"(a[2]), "r"(a[3]), "r"(b0), "r"(b1));
}

// ---------------- operand prep: fp32 -> bf16 hi/lo split ----------------
__global__ __launch_bounds__(256) void split_kernel(const float* __restrict__ src,
                                                    __nv_bfloat16* __restrict__ hi,
                                                    __nv_bfloat16* __restrict__ lo)
{
    const size_t i = ((size_t)blockIdx.x * 256 + threadIdx.x) * 4;
    float4 v = *(const float4*)(src + i);
    __nv_bfloat16 h0 = __float2bfloat16(v.x);
    __nv_bfloat16 h1 = __float2bfloat16(v.y);
    __nv_bfloat16 h2 = __float2bfloat16(v.z);
    __nv_bfloat16 h3 = __float2bfloat16(v.w);
    *(__nv_bfloat162*)(hi + i)     = __halves2bfloat162(h0, h1);
    *(__nv_bfloat162*)(hi + i + 2) = __halves2bfloat162(h2, h3);
    *(__nv_bfloat162*)(lo + i) =
        __halves2bfloat162(__float2bfloat16(v.x - __bfloat162float(h0)),
                           __float2bfloat16(v.y - __bfloat162float(h1)));
    *(__nv_bfloat162*)(lo + i + 2) =
        __halves2bfloat162(__float2bfloat16(v.z - __bfloat162float(h2)),
                           __float2bfloat16(v.w - __bfloat162float(h3)));
}

// ---------------- weight transpose + split: W[K][N] fp32 -> T[N][K] bf16 hi/lo ----------------
__global__ __launch_bounds__(256) void tsplit_kernel(const float* __restrict__ W,
                                                     __nv_bfloat16* __restrict__ Thi,
                                                     __nv_bfloat16* __restrict__ Tlo,
                                                     int K, int N)
{
    __shared__ float t[32][33];
    const int n0 = blockIdx.x * 32, k0 = blockIdx.y * 32;
    const int tx = threadIdx.x & 31, ty = threadIdx.x >> 5;   // ty 0..7
#pragma unroll
    for (int j = 0; j < 4; j++)
        t[ty * 4 + j][tx] = W[(size_t)(k0 + ty * 4 + j) * N + n0 + tx];
    __syncthreads();
#pragma unroll
    for (int j = 0; j < 4; j++) {
        const int n = ty * 4 + j;
        const float v = t[tx][n];
        __nv_bfloat16 h = __float2bfloat16(v);
        Thi[(size_t)(n0 + n) * K + k0 + tx] = h;
        Tlo[(size_t)(n0 + n) * K + k0 + tx] = __float2bfloat16(v - __bfloat162float(h));
    }
}

// ---------------- HMMA bf16x3 GEMM: C[M,N] = (Ahi+Alo)(Bhi+Blo)^T (+bias) ----------------
// CTA tile 128x128, 8 warps (warp tile 32x64), K-chunk 16.
// 3-stage cp.async ring, ONE __syncthreads per iteration:
//   wait(<=1 pending) -> sync -> issue loads for kt+2 -> LDSM(kt) -> MMA(kt)
// Stage written at kt ((kt+2)%3) was read at kt-1; all warps' kt-1 LDSMs retired
// before they passed this iteration's barrier, so the overwrite is race-free.
#define GROWB   48              // row stride bytes (24 bf16)
#define GTILE   (128 * GROWB)   // 6144
#define GSTAGE  (4 * GTILE)     // 24576
#define NSTAGE  3
#define GSMEM   (NSTAGE * GSTAGE)   // 73728 bytes (dynamic)
#define GT_AHI  0
#define GT_ALO  GTILE
#define GT_BHI  (2 * GTILE)
#define GT_BLO  (3 * GTILE)

__global__ __launch_bounds__(256, 2) void gemm_mma_kernel(
    const __nv_bfloat16* __restrict__ Ahi, const __nv_bfloat16* __restrict__ Alo,
    const __nv_bfloat16* __restrict__ Bhi, const __nv_bfloat16* __restrict__ Blo,
    float* __restrict__ C, const float* __restrict__ bias, int N, int K)
{
    extern __shared__ __align__(16) char smem[];
    const int tid  = threadIdx.x;
    const int lane = tid & 31;
    const int wid  = tid >> 5;
    const int bm = blockIdx.y * 128;
    const int bn = blockIdx.x * 128;
    const int wm = (wid & 3) * 32;
    const int wn = (wid >> 2) * 64;
    const int KT = K >> 4;
    const uint32_t sbase = smem_u32(smem);

    const __nv_bfloat16* gsrc[4] = { Ahi + (size_t)bm * K, Alo + (size_t)bm * K,
                                     Bhi + (size_t)bn * K, Blo + (size_t)bn * K };

    auto load_stage = [&](int s, int k0) {
#pragma unroll
        for (int t = 0; t < 4; t++) {
            const int linear = t * 256 + tid;      // 0..1023
            const int tile = linear >> 8;          // 0..3
            const int c    = linear & 255;
            const int row  = c >> 1;               // 0..127
            const int seg  = c & 1;                // 16B halves of 32B row
            const uint32_t dst = sbase + s * GSTAGE + tile * GTILE + row * GROWB + seg * 16;
            cp_async16(dst, (const char*)gsrc[tile] + ((size_t)row * K + k0) * 2 + seg * 16);
        }
        CP_COMMIT();
    };

    float acc[2][8][4];
#pragma unroll
    for (int mi = 0; mi < 2; mi++)
#pragma unroll
        for (int ni = 0; ni < 8; ni++)
#pragma unroll
            for (int j = 0; j < 4; j++) acc[mi][ni][j] = 0.0f;

    load_stage(0, 0);
    load_stage(1, 16);

    int s = 0;
    for (int kt = 0; kt < KT; kt++) {
        if (kt == KT - 1) CP_WAIT0(); else CP_WAIT1();
        __syncthreads();                            // stage s ready; prior reads retired

        // issue loads for kt+2 into the stage consumed at kt-1 (safe post-barrier)
        if (kt + 2 < KT) {
            int s2 = s + 2; if (s2 >= NSTAGE) s2 -= NSTAGE;
            load_stage(s2, (kt + 2) * 16);
        }

        const uint32_t st = sbase + s * GSTAGE;

        // ---- LDSM phase ----
        uint32_t ah[2][4], al[2][4];
#pragma unroll
        for (int mi = 0; mi < 2; mi++) {
            const int row = wm + mi * 16 + (lane & 15);
            const uint32_t off = row * GROWB + (lane >> 4) * 16;
            ldsm4(ah[mi], st + GT_AHI + off);
            ldsm4(al[mi], st + GT_ALO + off);
        }
        uint32_t bh[8][2], bl[8][2];
        {
            const int grp = lane >> 3;
            const int roff = (grp >> 1) * 8 + (lane & 7);
            const int koff = (grp & 1) * 16;
#pragma unroll
            for (int pi = 0; pi < 4; pi++) {
                const int nrow = wn + pi * 16 + roff;
                const uint32_t off = nrow * GROWB + koff;
                uint32_t r[4];
                ldsm4(r, st + GT_BHI + off);
                bh[pi * 2][0] = r[0]; bh[pi * 2][1] = r[1];
                bh[pi * 2 + 1][0] = r[2]; bh[pi * 2 + 1][1] = r[3];
                ldsm4(r, st + GT_BLO + off);
                bl[pi * 2][0] = r[0]; bl[pi * 2][1] = r[1];
                bl[pi * 2 + 1][0] = r[2]; bl[pi * 2 + 1][1] = r[3];
            }
        }

        // ---- MMA phase: hi*hi + hi*lo + lo*hi ----
#pragma unroll
        for (int mi = 0; mi < 2; mi++)
#pragma unroll
            for (int ni = 0; ni < 8; ni++) {
                mma16816(acc[mi][ni], ah[mi], bh[ni][0], bh[ni][1]);
                mma16816(acc[mi][ni], ah[mi], bl[ni][0], bl[ni][1]);
                mma16816(acc[mi][ni], al[mi], bh[ni][0], bh[ni][1]);
            }

        if (++s >= NSTAGE) s -= NSTAGE;
    }

    // epilogue: direct fp32 stores (+bias)
#pragma unroll
    for (int mi = 0; mi < 2; mi++)
#pragma unroll
        for (int ni = 0; ni < 8; ni++) {
            const int col = bn + wn + ni * 8 + (lane & 3) * 2;
            float b0 = 0.0f, b1 = 0.0f;
            if (bias) { b0 = bias[col]; b1 = bias[col + 1]; }
            const int r0 = bm + wm + mi * 16 + (lane >> 2);
            float2 v0 = { acc[mi][ni][0] + b0, acc[mi][ni][1] + b1 };
            float2 v1 = { acc[mi][ni][2] + b0, acc[mi][ni][3] + b1 };
            *(float2*)&C[(size_t)r0 * N + col] = v0;
            *(float2*)&C[(size_t)(r0 + 8) * N + col] = v1;
        }
}

// ---------------- depthwise conv (k=4, SAME: pad_lo=1) + silu ----------------
// xs-half -> g_xc (fp32); z-half -> g_chi/g_clo bf16 split directly.
__device__ __forceinline__ float silu_f(float v) {
    return __fdividef(v, 1.0f + __expf(-v));
}

__global__ __launch_bounds__(256) void conv_silu_kernel(
    const float* __restrict__ cwx, const float* __restrict__ cbx,
    const float* __restrict__ cwz, const float* __restrict__ cbz)
{
    const int c  = blockIdx.x * 256 + threadIdx.x;
    const int l0 = blockIdx.y * 8;
    const int b  = blockIdx.z;
    const float* base = g_xz + (size_t)b * SEQL * DINNER;

    const float wx0 = cwx[c], wx1 = cwx[DHALF + c], wx2 = cwx[2 * DHALF + c], wx3 = cwx[3 * DHALF + c];
    const float wz0 = cwz[c], wz1 = cwz[DHALF + c], wz2 = cwz[2 * DHALF + c], wz3 = cwz[3 * DHALF + c];
    const float bx = cbx[c], bz = cbz[c];

    float x0 = (l0 > 0) ? base[(size_t)(l0 - 1) * DINNER + c] : 0.0f;
    float x1 = base[(size_t)l0 * DINNER + c];
    float x2 = base[(size_t)(l0 + 1) * DINNER + c];
    float z0 = (l0 > 0) ? base[(size_t)(l0 - 1) * DINNER + DHALF + c] : 0.0f;
    float z1 = base[(size_t)l0 * DINNER + DHALF + c];
    float z2 = base[(size_t)(l0 + 1) * DINNER + DHALF + c];

#pragma unroll
    for (int t = 0; t < 8; t++) {
        const int l = l0 + t;
        const bool in = (l + 2 < SEQL);
        float x3 = in ? base[(size_t)(l + 2) * DINNER + c] : 0.0f;
        float z3 = in ? base[(size_t)(l + 2) * DINNER + DHALF + c] : 0.0f;
        float vx = fmaf(x0, wx0, fmaf(x1, wx1, fmaf(x2, wx2, fmaf(x3, wx3, bx))));
        float vz = fmaf(z0, wz0, fmaf(z1, wz1, fmaf(z2, wz2, fmaf(z3, wz3, bz))));
        g_xc[((size_t)b * SEQL + l) * DHALF + c] = silu_f(vx);
        const float sz = silu_f(vz);
        const __nv_bfloat16 h = __float2bfloat16(sz);
        const size_t zi = ((size_t)b * SEQL + l) * DINNER + DHALF + c;
        g_chi[zi] = h;
        g_clo[zi] = __float2bfloat16(sz - __bfloat162float(h));
        x0 = x1; x1 = x2; x2 = x3;
        z0 = z1; z1 = z2; z2 = z3;
    }
}

// ---------------- x_dbl = xs_conv @ W_xdbl (M=8192, K=1024, N=96) ----------------
__global__ __launch_bounds__(256) void gemm_xdbl_kernel(const float* __restrict__ Wx)
{
    __shared__ float As[32][32];
    __shared__ float Bs[32][96];
    const int tid = threadIdx.x;
    const int m0  = blockIdx.x * 32;
    const int tx  = tid & 7;
    const int ty  = tid >> 3;

    float acc[12];
#pragma unroll
    for (int j = 0; j < 12; j++) acc[j] = 0.0f;

    for (int k0 = 0; k0 < DHALF; k0 += 32) {
        {
            const int row = tid >> 3, c4 = tid & 7;
            *(float4*)&As[row][c4 * 4] =
                *(const float4*)&g_xc[(size_t)(m0 + row) * DHALF + k0 + c4 * 4];
        }
#pragma unroll
        for (int i = 0; i < 3; i++) {
            const int idx = i * 256 + tid;
            if (idx < 768) {
                const int row = idx / 24, c4 = idx % 24;
                *(float4*)&Bs[row][c4 * 4] =
                    *(const float4*)&Wx[(size_t)(k0 + row) * XDBL_N + c4 * 4];
            }
        }
        __syncthreads();
#pragma unroll
        for (int kk = 0; kk < 32; kk++) {
            const float a = As[ty][kk];
            float4 b0 = *(const float4*)&Bs[kk][tx * 12];
            float4 b1 = *(const float4*)&Bs[kk][tx * 12 + 4];
            float4 b2 = *(const float4*)&Bs[kk][tx * 12 + 8];
            acc[0]  = fmaf(a, b0.x, acc[0]);  acc[1]  = fmaf(a, b0.y, acc[1]);
            acc[2]  = fmaf(a, b0.z, acc[2]);  acc[3]  = fmaf(a, b0.w, acc[3]);
            acc[4]  = fmaf(a, b1.x, acc[4]);  acc[5]  = fmaf(a, b1.y, acc[5]);
            acc[6]  = fmaf(a, b1.z, acc[6]);  acc[7]  = fmaf(a, b1.w, acc[7]);
            acc[8]  = fmaf(a, b2.x, acc[8]);  acc[9]  = fmaf(a, b2.y, acc[9]);
            acc[10] = fmaf(a, b2.z, acc[10]); acc[11] = fmaf(a, b2.w, acc[11]);
        }
        __syncthreads();
    }
#pragma unroll
    for (int j = 0; j < 12; j++)
        g_xdbl[(size_t)(m0 + ty) * XDBL_N + tx * 12 + j] = acc[j];
}

// ---------------- delta = softplus(dt_low @ W_dt + 2*inv_dt)  (M=8192, K=64, N=1024) ----------------
__global__ __launch_bounds__(256) void gemm_dt_kernel(const float* __restrict__ Wdt,
                                                      const float* __restrict__ inv_dt)
{
    __shared__ float As[64][64];
    __shared__ float Bs[64][128];
    const int tid = threadIdx.x;
    const int n0  = blockIdx.x * 128;
    const int m0  = blockIdx.y * 64;

#pragma unroll
    for (int i = 0; i < 4; i++) {
        const int idx = i * 256 + tid;
        const int row = idx >> 4, c4 = idx & 15;
        *(float4*)&As[row][c4 * 4] =
            *(const float4*)&g_xdbl[(size_t)(m0 + row) * XDBL_N + c4 * 4];
    }
#pragma unroll
    for (int i = 0; i < 8; i++) {
        const int idx = i * 256 + tid;
        const int row = idx >> 5, c4 = idx & 31;
        *(float4*)&Bs[row][c4 * 4] =
            *(const float4*)&Wdt[(size_t)row * DHALF + n0 + c4 * 4];
    }
    __syncthreads();

    const int ty = tid >> 5;
    const int tx = tid & 31;
    float acc[8][4];
#pragma unroll
    for (int i = 0; i < 8; i++)
#pragma unroll
        for (int j = 0; j < 4; j++) acc[i][j] = 0.0f;

#pragma unroll 8
    for (int k = 0; k < 64; k++) {
        float4 b = *(const float4*)&Bs[k][tx * 4];
#pragma unroll
        for (int i = 0; i < 8; i++) {
            const float a = As[ty * 8 + i][k];
            acc[i][0] = fmaf(a, b.x, acc[i][0]);
            acc[i][1] = fmaf(a, b.y, acc[i][1]);
            acc[i][2] = fmaf(a, b.z, acc[i][2]);
            acc[i][3] = fmaf(a, b.w, acc[i][3]);
        }
    }

    float iv[4];
#pragma unroll
    for (int j = 0; j < 4; j++) iv[j] = 2.0f * inv_dt[n0 + tx * 4 + j];
#pragma unroll
    for (int i = 0; i < 8; i++) {
        float d[4];
#pragma unroll
        for (int j = 0; j < 4; j++) {
            float xv = acc[i][j] + iv[j];
            d[j] = (xv > 15.0f) ? xv : log1pf(__expf(xv));
        }
        float4 o = {d[0], d[1], d[2], d[3]};
        *(float4*)&g_delta[(size_t)(m0 + ty * 8 + i) * DHALF + n0 + tx * 4] = o;
    }
}

// ---------------- scan phase A: per-chunk local end-state H and sum-of-delta S ----------------
__global__ __launch_bounds__(256) void scan_a_kernel()
{
    __shared__ float Bsm[TC][DSTATE];
    const int b  = blockIdx.z;
    const int dc = blockIdx.y;
    const int ch = blockIdx.x;
    const int tid = threadIdx.x;
    const int d  = dc * 256 + tid;
    const int m0 = b * SEQL + ch * TC;

#pragma unroll
    for (int i = 0; i < 4; i++) {
        const int idx = i * 256 + tid;
        const int t = idx >> 4, n = idx & 15;
        Bsm[t][n] = g_xdbl[(size_t)(m0 + t) * XDBL_N + DTRANK + n];
    }
    __syncthreads();

    float h[DSTATE];
#pragma unroll
    for (int n = 0; n < DSTATE; n++) h[n] = 0.0f;
    float S = 0.0f;

    for (int t = 0; t < TC; t++) {
        const float delta = g_delta[(size_t)(m0 + t) * DHALF + d];
        const float u     = g_xc  [(size_t)(m0 + t) * DHALF + d];
        const float e  = __expf(-delta);
        const float du = delta * u;
        S += delta;
        float en = e;
#pragma unroll
        for (int n = 0; n < DSTATE; n++) {
            h[n] = fmaf(en, h[n], du * Bsm[t][n]);
            en *= e;
        }
    }
    const int cidx = (b * NCH + ch) * DHALF + d;
    g_S[cidx] = S;
    float* Hp = &g_H[(size_t)cidx * DSTATE];
#pragma unroll
    for (int q = 0; q < 4; q++) {
        float4 o = {h[q * 4], h[q * 4 + 1], h[q * 4 + 2], h[q * 4 + 3]};
        *(float4*)&Hp[q * 4] = o;
    }
}

// ---------------- scan phase B: stitch chunk boundaries ----------------
__global__ __launch_bounds__(256) void scan_b_kernel()
{
    const int g = blockIdx.x * 256 + threadIdx.x;
    const int n = g & 15;
    const int d = (g >> 4) & (DHALF - 1);
    const int b = g >> 14;
    const float nn = -(float)(n + 1);

    float hin = 0.0f;
    for (int c = 0; c < NCH; c++) {
        const int cidx = (b * NCH + c) * DHALF + d;
        const float S  = g_S[cidx];
        const float Hc = g_H[(size_t)cidx * DSTATE + n];
        const float P  = __expf(nn * S);
        const float nxt = fmaf(P, hin, Hc);
        g_H[(size_t)cidx * DSTATE + n] = hin;
        hin = nxt;
    }
}

// ---------------- scan phase C: exact recurrence; emit y as bf16 hi/lo ----------------
__global__ __launch_bounds__(256) void scan_c_kernel(const float* __restrict__ Dvec)
{
    __shared__ float Bsm[TC][DSTATE];
    __shared__ float Csm[TC][DSTATE];
    const int b  = blockIdx.z;
    const int dc = blockIdx.y;
    const int ch = blockIdx.x;
    const int tid = threadIdx.x;
    const int d  = dc * 256 + tid;
    const int m0 = b * SEQL + ch * TC;

#pragma unroll
    for (int i = 0; i < 8; i++) {
        const int idx = i * 256 + tid;
        const int t = idx >> 5, q = idx & 31;
        const float v = g_xdbl[(size_t)(m0 + t) * XDBL_N + DTRANK + q];
        if (q < 16) Bsm[t][q] = v;
        else        Csm[t][q - 16] = v;
    }

    const int cidx = (b * NCH + ch) * DHALF + d;
    const float* Hp = &g_H[(size_t)cidx * DSTATE];
    float h[DSTATE];
#pragma unroll
    for (int q = 0; q < 4; q++) {
        float4 v = *(const float4*)&Hp[q * 4];
        h[q * 4] = v.x; h[q * 4 + 1] = v.y; h[q * 4 + 2] = v.z; h[q * 4 + 3] = v.w;
    }
    const float Dv = Dvec[d];
    __syncthreads();

    for (int t = 0; t < TC; t++) {
        const float delta = g_delta[(size_t)(m0 + t) * DHALF + d];
        const float u     = g_xc  [(size_t)(m0 + t) * DHALF + d];
        const float e  = __expf(-delta);
        const float du = delta * u;
        float en = e;
        float y = 0.0f;
#pragma unroll
        for (int n = 0; n < DSTATE; n++) {
            h[n] = fmaf(en, h[n], du * Bsm[t][n]);
            y = fmaf(h[n], Csm[t][n], y);
            en *= e;
        }
        const float yv = fmaf(u, Dv, y);
        const __nv_bfloat16 hh = __float2bfloat16(yv);
        const size_t yi = (size_t)(m0 + t) * DINNER + d;
        g_chi[yi] = hh;
        g_clo[yi] = __float2bfloat16(yv - __bfloat162float(hh));
    }
}

// ---------------- launcher ----------------
extern "C" void kernel_launch(void* const* d_in, const int* in_sizes, int n_in,
                              void* d_out, int out_size)
{
    (void)in_sizes; (void)n_in; (void)out_size;
    const float* x     = (const float*)d_in[0];
    const float* W_in  = (const float*)d_in[1];
    const float* cxw   = (const float*)d_in[2];
    const float* cxb   = (const float*)d_in[3];
    const float* czw   = (const float*)d_in[4];
    const float* czb   = (const float*)d_in[5];
    const float* Wxdbl = (const float*)d_in[6];
    const float* Wdt   = (const float*)d_in[7];
    const float* invdt = (const float*)d_in[8];
    const float* Dvec  = (const float*)d_in[9];
    const float* W_out = (const float*)d_in[10];
    const float* b_out = (const float*)d_in[11];
    float* out = (float*)d_out;

    cudaFuncSetAttribute(gemm_mma_kernel,
                         cudaFuncAttributeMaxDynamicSharedMemorySize, GSMEM);

    __nv_bfloat16 *xhi, *xlo, *chi, *clo, *binhi, *binlo, *bouthi, *boutlo;
    float *gxz = nullptr;
    cudaGetSymbolAddress((void**)&xhi, g_xhi);
    cudaGetSymbolAddress((void**)&xlo, g_xlo);
    cudaGetSymbolAddress((void**)&chi, g_chi);
    cudaGetSymbolAddress((void**)&clo, g_clo);
    cudaGetSymbolAddress((void**)&binhi, g_binhi);
    cudaGetSymbolAddress((void**)&binlo, g_binlo);
    cudaGetSymbolAddress((void**)&bouthi, g_bouthi);
    cudaGetSymbolAddress((void**)&boutlo, g_boutlo);
    cudaGetSymbolAddress((void**)&gxz, g_xz);

    // 1. split x into bf16 hi/lo; transpose+split W_in / W_out
    split_kernel<<<(MROWS * DMODEL) / 1024, 256>>>(x, xhi, xlo);
    tsplit_kernel<<<dim3(DINNER / 32, DMODEL / 32), 256>>>(W_in, binhi, binlo, DMODEL, DINNER);
    tsplit_kernel<<<dim3(DMODEL / 32, DINNER / 32), 256>>>(W_out, bouthi, boutlo, DINNER, DMODEL);
    // 2. xz = x @ W_in  (HMMA bf16x3)
    gemm_mma_kernel<<<dim3(DINNER / 128, MROWS / 128), 256, GSMEM>>>(
        xhi, xlo, binhi, binlo, gxz, nullptr, DINNER, DMODEL);
    // 3. depthwise conv + silu (xs -> g_xc fp32; z -> g_chi/g_clo bf16)
    conv_silu_kernel<<<dim3(DHALF / 256, SEQL / 8, BSZ), 256>>>(cxw, cxb, czw, czb);
    // 4. x_dbl = xs @ W_xdbl
    gemm_xdbl_kernel<<<MROWS / 32, 256>>>(Wxdbl);
    // 5. delta = softplus(dt_low @ W_dt + 2*inv_dt)
    gemm_dt_kernel<<<dim3(DHALF / 128, MROWS / 64), 256>>>(Wdt, invdt);
    // 6-8. chunked selective scan (y -> g_chi/g_clo bf16)
    scan_a_kernel<<<dim3(NCH, DHALF / 256, BSZ), 256>>>();
    scan_b_kernel<<<(BSZ * DHALF * DSTATE) / 256, 256>>>();
    scan_c_kernel<<<dim3(NCH, DHALF / 256, BSZ), 256>>>(Dvec);
    // 9. out = [y, z] @ W_out + b_out  (HMMA bf16x3)
    gemm_mma_kernel<<<dim3(DMODEL / 128, MROWS / 128), 256, GSMEM>>>(
        chi, clo, bouthi, boutlo, out, b_out, DMODEL, DINNER);
}

// round 14
// speedup vs baseline: 1.1534x; 1.1534x over previous
#include <cuda_runtime.h>
#include <cuda_bf16.h>
#include <math.h>
#include <stdint.h>

// ---------------- problem constants ----------------
#define BSZ     4
#define SEQL    2048
#define DMODEL  1024
#define DINNER  2048
#define DHALF   1024
#define DSTATE  16
#define DTRANK  64
#define MROWS   (BSZ * SEQL)            // 8192
#define XDBL_N  (DTRANK + 2 * DSTATE)   // 96
#define TC      64                      // scan chunk length
#define NCH     (SEQL / TC)             // 32 chunks

// ---------------- scratch (device globals; no allocation allowed) ----------------
__device__ __align__(16) float g_xz   [MROWS * DINNER];
__device__ __align__(16) float g_xc   [MROWS * DHALF];
__device__ __align__(16) float g_xdbl [MROWS * XDBL_N];
__device__ __align__(16) float g_delta[MROWS * DHALF];
__device__ __align__(16) float g_S    [BSZ * NCH * DHALF];
__device__ __align__(16) float g_H    [BSZ * NCH * DHALF * DSTATE];

// bf16 split operands for tensor-core GEMMs
__device__ __align__(16) __nv_bfloat16 g_xhi   [MROWS * DMODEL];
__device__ __align__(16) __nv_bfloat16 g_xlo   [MROWS * DMODEL];
__device__ __align__(16) __nv_bfloat16 g_chi   [MROWS * DINNER];   // [y | z] hi
__device__ __align__(16) __nv_bfloat16 g_clo   [MROWS * DINNER];   // [y | z] lo
__device__ __align__(16) __nv_bfloat16 g_binhi [DINNER * DMODEL];  // W_in^T  [2048][1024]
__device__ __align__(16) __nv_bfloat16 g_binlo [DINNER * DMODEL];
__device__ __align__(16) __nv_bfloat16 g_bouthi[DMODEL * DINNER];  // W_out^T [1024][2048]
__device__ __align__(16) __nv_bfloat16 g_boutlo[DMODEL * DINNER];

// ---------------- PTX helpers (sm_80-class: cp.async / ldmatrix / mma.sync) ----------------
__device__ __forceinline__ uint32_t smem_u32(const void* p) {
    uint32_t a;
    asm("{ .reg .u64 t; cvta.to.shared.u64 t, %1; cvt.u32.u64 %0, t; }" : "=r"(a) : "l"(p));
    return a;
}
__device__ __forceinline__ void cp_async16(uint32_t dst, const void* src) {
    asm volatile("cp.async.cg.shared.global [%0], [%1], 16;" :: "r"(dst), "l"(src));
}
#define CP_COMMIT() asm volatile("cp.async.commit_group;" ::: "memory")
#define CP_WAIT1()  asm volatile("cp.async.wait_group 1;" ::: "memory")
#define CP_WAIT0()  asm volatile("cp.async.wait_group 0;" ::: "memory")

__device__ __forceinline__ void ldsm4(uint32_t (&r)[4], uint32_t addr) {
    asm volatile("ldmatrix.sync.aligned.m8n8.x4.shared.b16 {%0,%1,%2,%3}, [%4];"
        : "=r"(r[0]), "=r"(r[1]), "=r"(r[2]), "=r"(r[3]) : "r"(addr));
}
__device__ __forceinline__ void mma16816(float (&c)[4], const uint32_t (&a)[4],
                                         uint32_t b0, uint32_t b1) {
    asm volatile("mma.sync.aligned.m16n8k16.row.col.f32.bf16.bf16.f32 "
        "{%0,%1,%2,%3}, {%4,%5,%6,%7}, {%8,%9}, {%0,%1,%2,%3};"
        : "+f"(c[0]), "+f"(c[1]), "+f"(c[2]), "+f"(c[3])
        : "r"(a[0]), "r"(a[1]), "r"(a[2]), "r"(a[3]), "r"(b0), "r"(b1));
}

// ---------------- operand prep: fp32 -> bf16 hi/lo split ----------------
__global__ __launch_bounds__(256) void split_kernel(const float* __restrict__ src,
                                                    __nv_bfloat16* __restrict__ hi,
                                                    __nv_bfloat16* __restrict__ lo)
{
    const size_t i = ((size_t)blockIdx.x * 256 + threadIdx.x) * 4;
    float4 v = *(const float4*)(src + i);
    __nv_bfloat16 h0 = __float2bfloat16(v.x);
    __nv_bfloat16 h1 = __float2bfloat16(v.y);
    __nv_bfloat16 h2 = __float2bfloat16(v.z);
    __nv_bfloat16 h3 = __float2bfloat16(v.w);
    *(__nv_bfloat162*)(hi + i)     = __halves2bfloat162(h0, h1);
    *(__nv_bfloat162*)(hi + i + 2) = __halves2bfloat162(h2, h3);
    *(__nv_bfloat162*)(lo + i) =
        __halves2bfloat162(__float2bfloat16(v.x - __bfloat162float(h0)),
                           __float2bfloat16(v.y - __bfloat162float(h1)));
    *(__nv_bfloat162*)(lo + i + 2) =
        __halves2bfloat162(__float2bfloat16(v.z - __bfloat162float(h2)),
                           __float2bfloat16(v.w - __bfloat162float(h3)));
}

// ---------------- weight transpose + split: W[K][N] fp32 -> T[N][K] bf16 hi/lo ----------------
__global__ __launch_bounds__(256) void tsplit_kernel(const float* __restrict__ W,
                                                     __nv_bfloat16* __restrict__ Thi,
                                                     __nv_bfloat16* __restrict__ Tlo,
                                                     int K, int N)
{
    __shared__ float t[32][33];
    const int n0 = blockIdx.x * 32, k0 = blockIdx.y * 32;
    const int tx = threadIdx.x & 31, ty = threadIdx.x >> 5;   // ty 0..7
#pragma unroll
    for (int j = 0; j < 4; j++)
        t[ty * 4 + j][tx] = W[(size_t)(k0 + ty * 4 + j) * N + n0 + tx];
    __syncthreads();
#pragma unroll
    for (int j = 0; j < 4; j++) {
        const int n = ty * 4 + j;
        const float v = t[tx][n];
        __nv_bfloat16 h = __float2bfloat16(v);
        Thi[(size_t)(n0 + n) * K + k0 + tx] = h;
        Tlo[(size_t)(n0 + n) * K + k0 + tx] = __float2bfloat16(v - __bfloat162float(h));
    }
}

// ---------------- HMMA bf16x3 GEMM: C[M,N] = (Ahi+Alo)(Bhi+Blo)^T (+bias) ----------------
// CTA tile 128x128, 8 warps (warp tile 32x64), K-chunk 32 (two k16 halves),
// 2-stage cp.async ring (R11-proven ordering, amortized over 2x MMAs):
//   wait -> sync -> LDSM(h0) -> MMA(h0) -> LDSM(h1) -> sync -> issue next -> MMA(h1)
#define GROWB   80                  // row stride bytes (64B data + 16B pad, conflict-free)
#define GTILE   (128 * GROWB)       // 10240
#define GSTAGE  (4 * GTILE)         // 40960
#define GSMEM   (2 * GSTAGE)        // 81920 bytes dynamic
#define GT_AHI  0
#define GT_ALO  GTILE
#define GT_BHI  (2 * GTILE)
#define GT_BLO  (3 * GTILE)

__global__ __launch_bounds__(256, 2) void gemm_mma_kernel(
    const __nv_bfloat16* __restrict__ Ahi, const __nv_bfloat16* __restrict__ Alo,
    const __nv_bfloat16* __restrict__ Bhi, const __nv_bfloat16* __restrict__ Blo,
    float* __restrict__ C, const float* __restrict__ bias, int N, int K)
{
    extern __shared__ __align__(16) char smem[];
    const int tid  = threadIdx.x;
    const int lane = tid & 31;
    const int wid  = tid >> 5;
    const int bm = blockIdx.y * 128;
    const int bn = blockIdx.x * 128;
    const int wm = (wid & 3) * 32;
    const int wn = (wid >> 2) * 64;
    const int KT = K >> 5;                 // chunks of 32
    const uint32_t sbase = smem_u32(smem);

    const __nv_bfloat16* gsrc[4] = { Ahi + (size_t)bm * K, Alo + (size_t)bm * K,
                                     Bhi + (size_t)bn * K, Blo + (size_t)bn * K };

    // one stage: 4 tiles x 128 rows x 64 data bytes (stride 80)
    auto load_stage = [&](int s, int k0) {
#pragma unroll
        for (int t = 0; t < 8; t++) {
            const int linear = t * 256 + tid;      // 0..2047
            const int tile = linear >> 9;          // 0..3
            const int c    = linear & 511;
            const int row  = c >> 2;               // 0..127
            const int seg  = c & 3;                // 4 x 16B per row
            const uint32_t dst = sbase + s * GSTAGE + tile * GTILE + row * GROWB + seg * 16;
            cp_async16(dst, (const char*)gsrc[tile] + ((size_t)row * K + k0) * 2 + seg * 16);
        }
        CP_COMMIT();
    };

    float acc[2][8][4];
#pragma unroll
    for (int mi = 0; mi < 2; mi++)
#pragma unroll
        for (int ni = 0; ni < 8; ni++)
#pragma unroll
            for (int j = 0; j < 4; j++) acc[mi][ni][j] = 0.0f;

    load_stage(0, 0);
    if (KT > 1) load_stage(1, 32);

    uint32_t ah[2][4], al[2][4];
    uint32_t bh[8][2], bl[8][2];

    auto ldsm_half = [&](uint32_t st, int half) {
        const uint32_t hoff = half * 32;           // k16 half -> +32B
#pragma unroll
        for (int mi = 0; mi < 2; mi++) {
            const int row = wm + mi * 16 + (lane & 15);
            const uint32_t off = row * GROWB + (lane >> 4) * 16 + hoff;
            ldsm4(ah[mi], st + GT_AHI + off);
            ldsm4(al[mi], st + GT_ALO + off);
        }
        const int grp = lane >> 3;
        const int roff = (grp >> 1) * 8 + (lane & 7);
        const int koff = (grp & 1) * 16 + hoff;
#pragma unroll
        for (int pi = 0; pi < 4; pi++) {
            const int nrow = wn + pi * 16 + roff;
            const uint32_t off = nrow * GROWB + koff;
            uint32_t r[4];
            ldsm4(r, st + GT_BHI + off);
            bh[pi * 2][0] = r[0]; bh[pi * 2][1] = r[1];
            bh[pi * 2 + 1][0] = r[2]; bh[pi * 2 + 1][1] = r[3];
            ldsm4(r, st + GT_BLO + off);
            bl[pi * 2][0] = r[0]; bl[pi * 2][1] = r[1];
            bl[pi * 2 + 1][0] = r[2]; bl[pi * 2 + 1][1] = r[3];
        }
    };

    auto mma_all = [&]() {
#pragma unroll
        for (int mi = 0; mi < 2; mi++)
#pragma unroll
            for (int ni = 0; ni < 8; ni++) {
                mma16816(acc[mi][ni], ah[mi], bh[ni][0], bh[ni][1]);
                mma16816(acc[mi][ni], ah[mi], bl[ni][0], bl[ni][1]);
                mma16816(acc[mi][ni], al[mi], bh[ni][0], bh[ni][1]);
            }
    };

    for (int kt = 0; kt < KT; kt++) {
        const int s = kt & 1;
        if (kt == KT - 1) CP_WAIT0(); else CP_WAIT1();
        __syncthreads();                            // stage s ready

        const uint32_t st = sbase + s * GSTAGE;
        ldsm_half(st, 0);
        mma_all();                                  // half 0
        ldsm_half(st, 1);
        __syncthreads();                            // all reads of stage s done
        if (kt + 2 < KT) load_stage(s, (kt + 2) * 32);   // overlaps half-1 MMAs
        mma_all();                                  // half 1
    }

    // epilogue: direct fp32 stores (+bias)
#pragma unroll
    for (int mi = 0; mi < 2; mi++)
#pragma unroll
        for (int ni = 0; ni < 8; ni++) {
            const int col = bn + wn + ni * 8 + (lane & 3) * 2;
            float b0 = 0.0f, b1 = 0.0f;
            if (bias) { b0 = bias[col]; b1 = bias[col + 1]; }
            const int r0 = bm + wm + mi * 16 + (lane >> 2);
            float2 v0 = { acc[mi][ni][0] + b0, acc[mi][ni][1] + b1 };
            float2 v1 = { acc[mi][ni][2] + b0, acc[mi][ni][3] + b1 };
            *(float2*)&C[(size_t)r0 * N + col] = v0;
            *(float2*)&C[(size_t)(r0 + 8) * N + col] = v1;
        }
}

// ---------------- depthwise conv (k=4, SAME: pad_lo=1) + silu ----------------
__device__ __forceinline__ float silu_f(float v) {
    return __fdividef(v, 1.0f + __expf(-v));
}

__global__ __launch_bounds__(256) void conv_silu_kernel(
    const float* __restrict__ cwx, const float* __restrict__ cbx,
    const float* __restrict__ cwz, const float* __restrict__ cbz)
{
    const int c  = blockIdx.x * 256 + threadIdx.x;
    const int l0 = blockIdx.y * 8;
    const int b  = blockIdx.z;
    const float* base = g_xz + (size_t)b * SEQL * DINNER;

    const float wx0 = cwx[c], wx1 = cwx[DHALF + c], wx2 = cwx[2 * DHALF + c], wx3 = cwx[3 * DHALF + c];
    const float wz0 = cwz[c], wz1 = cwz[DHALF + c], wz2 = cwz[2 * DHALF + c], wz3 = cwz[3 * DHALF + c];
    const float bx = cbx[c], bz = cbz[c];

    float x0 = (l0 > 0) ? base[(size_t)(l0 - 1) * DINNER + c] : 0.0f;
    float x1 = base[(size_t)l0 * DINNER + c];
    float x2 = base[(size_t)(l0 + 1) * DINNER + c];
    float z0 = (l0 > 0) ? base[(size_t)(l0 - 1) * DINNER + DHALF + c] : 0.0f;
    float z1 = base[(size_t)l0 * DINNER + DHALF + c];
    float z2 = base[(size_t)(l0 + 1) * DINNER + DHALF + c];

#pragma unroll
    for (int t = 0; t < 8; t++) {
        const int l = l0 + t;
        const bool in = (l + 2 < SEQL);
        float x3 = in ? base[(size_t)(l + 2) * DINNER + c] : 0.0f;
        float z3 = in ? base[(size_t)(l + 2) * DINNER + DHALF + c] : 0.0f;
        float vx = fmaf(x0, wx0, fmaf(x1, wx1, fmaf(x2, wx2, fmaf(x3, wx3, bx))));
        float vz = fmaf(z0, wz0, fmaf(z1, wz1, fmaf(z2, wz2, fmaf(z3, wz3, bz))));
        g_xc[((size_t)b * SEQL + l) * DHALF + c] = silu_f(vx);
        const float sz = silu_f(vz);
        const __nv_bfloat16 h = __float2bfloat16(sz);
        const size_t zi = ((size_t)b * SEQL + l) * DINNER + DHALF + c;
        g_chi[zi] = h;
        g_clo[zi] = __float2bfloat16(sz - __bfloat162float(h));
        x0 = x1; x1 = x2; x2 = x3;
        z0 = z1; z1 = z2; z2 = z3;
    }
}

// ---------------- x_dbl = xs_conv @ W_xdbl (M=8192, K=1024, N=96) ----------------
__global__ __launch_bounds__(256) void gemm_xdbl_kernel(const float* __restrict__ Wx)
{
    __shared__ float As[32][32];
    __shared__ float Bs[32][96];
    const int tid = threadIdx.x;
    const int m0  = blockIdx.x * 32;
    const int tx  = tid & 7;
    const int ty  = tid >> 3;

    float acc[12];
#pragma unroll
    for (int j = 0; j < 12; j++) acc[j] = 0.0f;

    for (int k0 = 0; k0 < DHALF; k0 += 32) {
        {
            const int row = tid >> 3, c4 = tid & 7;
            *(float4*)&As[row][c4 * 4] =
                *(const float4*)&g_xc[(size_t)(m0 + row) * DHALF + k0 + c4 * 4];
        }
#pragma unroll
        for (int i = 0; i < 3; i++) {
            const int idx = i * 256 + tid;
            if (idx < 768) {
                const int row = idx / 24, c4 = idx % 24;
                *(float4*)&Bs[row][c4 * 4] =
                    *(const float4*)&Wx[(size_t)(k0 + row) * XDBL_N + c4 * 4];
            }
        }
        __syncthreads();
#pragma unroll
        for (int kk = 0; kk < 32; kk++) {
            const float a = As[ty][kk];
            float4 b0 = *(const float4*)&Bs[kk][tx * 12];
            float4 b1 = *(const float4*)&Bs[kk][tx * 12 + 4];
            float4 b2 = *(const float4*)&Bs[kk][tx * 12 + 8];
            acc[0]  = fmaf(a, b0.x, acc[0]);  acc[1]  = fmaf(a, b0.y, acc[1]);
            acc[2]  = fmaf(a, b0.z, acc[2]);  acc[3]  = fmaf(a, b0.w, acc[3]);
            acc[4]  = fmaf(a, b1.x, acc[4]);  acc[5]  = fmaf(a, b1.y, acc[5]);
            acc[6]  = fmaf(a, b1.z, acc[6]);  acc[7]  = fmaf(a, b1.w, acc[7]);
            acc[8]  = fmaf(a, b2.x, acc[8]);  acc[9]  = fmaf(a, b2.y, acc[9]);
            acc[10] = fmaf(a, b2.z, acc[10]); acc[11] = fmaf(a, b2.w, acc[11]);
        }
        __syncthreads();
    }
#pragma unroll
    for (int j = 0; j < 12; j++)
        g_xdbl[(size_t)(m0 + ty) * XDBL_N + tx * 12 + j] = acc[j];
}

// ---------------- delta = softplus(dt_low @ W_dt + 2*inv_dt)  (M=8192, K=64, N=1024) ----------------
__global__ __launch_bounds__(256) void gemm_dt_kernel(const float* __restrict__ Wdt,
                                                      const float* __restrict__ inv_dt)
{
    __shared__ float As[64][64];
    __shared__ float Bs[64][128];
    const int tid = threadIdx.x;
    const int n0  = blockIdx.x * 128;
    const int m0  = blockIdx.y * 64;

#pragma unroll
    for (int i = 0; i < 4; i++) {
        const int idx = i * 256 + tid;
        const int row = idx >> 4, c4 = idx & 15;
        *(float4*)&As[row][c4 * 4] =
            *(const float4*)&g_xdbl[(size_t)(m0 + row) * XDBL_N + c4 * 4];
    }
#pragma unroll
    for (int i = 0; i < 8; i++) {
        const int idx = i * 256 + tid;
        const int row = idx >> 5, c4 = idx & 31;
        *(float4*)&Bs[row][c4 * 4] =
            *(const float4*)&Wdt[(size_t)row * DHALF + n0 + c4 * 4];
    }
    __syncthreads();

    const int ty = tid >> 5;
    const int tx = tid & 31;
    float acc[8][4];
#pragma unroll
    for (int i = 0; i < 8; i++)
#pragma unroll
        for (int j = 0; j < 4; j++) acc[i][j] = 0.0f;

#pragma unroll 8
    for (int k = 0; k < 64; k++) {
        float4 b = *(const float4*)&Bs[k][tx * 4];
#pragma unroll
        for (int i = 0; i < 8; i++) {
            const float a = As[ty * 8 + i][k];
            acc[i][0] = fmaf(a, b.x, acc[i][0]);
            acc[i][1] = fmaf(a, b.y, acc[i][1]);
            acc[i][2] = fmaf(a, b.z, acc[i][2]);
            acc[i][3] = fmaf(a, b.w, acc[i][3]);
        }
    }

    float iv[4];
#pragma unroll
    for (int j = 0; j < 4; j++) iv[j] = 2.0f * inv_dt[n0 + tx * 4 + j];
#pragma unroll
    for (int i = 0; i < 8; i++) {
        float d[4];
#pragma unroll
        for (int j = 0; j < 4; j++) {
            float xv = acc[i][j] + iv[j];
            d[j] = (xv > 15.0f) ? xv : log1pf(__expf(xv));
        }
        float4 o = {d[0], d[1], d[2], d[3]};
        *(float4*)&g_delta[(size_t)(m0 + ty * 8 + i) * DHALF + n0 + tx * 4] = o;
    }
}

// ---------------- scan phase A: per-chunk local end-state H and sum-of-delta S ----------------
__global__ __launch_bounds__(256) void scan_a_kernel()
{
    __shared__ float Bsm[TC][DSTATE];
    const int b  = blockIdx.z;
    const int dc = blockIdx.y;
    const int ch = blockIdx.x;
    const int tid = threadIdx.x;
    const int d  = dc * 256 + tid;
    const int m0 = b * SEQL + ch * TC;

#pragma unroll
    for (int i = 0; i < 4; i++) {
        const int idx = i * 256 + tid;
        const int t = idx >> 4, n = idx & 15;
        Bsm[t][n] = g_xdbl[(size_t)(m0 + t) * XDBL_N + DTRANK + n];
    }
    __syncthreads();

    float h[DSTATE];
#pragma unroll
    for (int n = 0; n < DSTATE; n++) h[n] = 0.0f;
    float S = 0.0f;

    for (int t = 0; t < TC; t++) {
        const float delta = g_delta[(size_t)(m0 + t) * DHALF + d];
        const float u     = g_xc  [(size_t)(m0 + t) * DHALF + d];
        const float e  = __expf(-delta);
        const float du = delta * u;
        S += delta;
        float en = e;
#pragma unroll
        for (int n = 0; n < DSTATE; n++) {
            h[n] = fmaf(en, h[n], du * Bsm[t][n]);
            en *= e;
        }
    }
    const int cidx = (b * NCH + ch) * DHALF + d;
    g_S[cidx] = S;
    float* Hp = &g_H[(size_t)cidx * DSTATE];
#pragma unroll
    for (int q = 0; q < 4; q++) {
        float4 o = {h[q * 4], h[q * 4 + 1], h[q * 4 + 2], h[q * 4 + 3]};
        *(float4*)&Hp[q * 4] = o;
    }
}

// ---------------- scan phase B: stitch chunk boundaries ----------------
__global__ __launch_bounds__(256) void scan_b_kernel()
{
    const int g = blockIdx.x * 256 + threadIdx.x;
    const int n = g & 15;
    const int d = (g >> 4) & (DHALF - 1);
    const int b = g >> 14;
    const float nn = -(float)(n + 1);

    float hin = 0.0f;
    for (int c = 0; c < NCH; c++) {
        const int cidx = (b * NCH + c) * DHALF + d;
        const float S  = g_S[cidx];
        const float Hc = g_H[(size_t)cidx * DSTATE + n];
        const float P  = __expf(nn * S);
        const float nxt = fmaf(P, hin, Hc);
        g_H[(size_t)cidx * DSTATE + n] = hin;
        hin = nxt;
    }
}

// ---------------- scan phase C: exact recurrence; emit y as bf16 hi/lo ----------------
__global__ __launch_bounds__(256) void scan_c_kernel(const float* __restrict__ Dvec)
{
    __shared__ float Bsm[TC][DSTATE];
    __shared__ float Csm[TC][DSTATE];
    const int b  = blockIdx.z;
    const int dc = blockIdx.y;
    const int ch = blockIdx.x;
    const int tid = threadIdx.x;
    const int d  = dc * 256 + tid;
    const int m0 = b * SEQL + ch * TC;

#pragma unroll
    for (int i = 0; i < 8; i++) {
        const int idx = i * 256 + tid;
        const int t = idx >> 5, q = idx & 31;
        const float v = g_xdbl[(size_t)(m0 + t) * XDBL_N + DTRANK + q];
        if (q < 16) Bsm[t][q] = v;
        else        Csm[t][q - 16] = v;
    }

    const int cidx = (b * NCH + ch) * DHALF + d;
    const float* Hp = &g_H[(size_t)cidx * DSTATE];
    float h[DSTATE];
#pragma unroll
    for (int q = 0; q < 4; q++) {
        float4 v = *(const float4*)&Hp[q * 4];
        h[q * 4] = v.x; h[q * 4 + 1] = v.y; h[q * 4 + 2] = v.z; h[q * 4 + 3] = v.w;
    }
    const float Dv = Dvec[d];
    __syncthreads();

    for (int t = 0; t < TC; t++) {
        const float delta = g_delta[(size_t)(m0 + t) * DHALF + d];
        const float u     = g_xc  [(size_t)(m0 + t) * DHALF + d];
        const float e  = __expf(-delta);
        const float du = delta * u;
        float en = e;
        float y = 0.0f;
#pragma unroll
        for (int n = 0; n < DSTATE; n++) {
            h[n] = fmaf(en, h[n], du * Bsm[t][n]);
            y = fmaf(h[n], Csm[t][n], y);
            en *= e;
        }
        const float yv = fmaf(u, Dv, y);
        const __nv_bfloat16 hh = __float2bfloat16(yv);
        const size_t yi = (size_t)(m0 + t) * DINNER + d;
        g_chi[yi] = hh;
        g_clo[yi] = __float2bfloat16(yv - __bfloat162float(hh));
    }
}

// ---------------- launcher ----------------
extern "C" void kernel_launch(void* const* d_in, const int* in_sizes, int n_in,
                              void* d_out, int out_size)
{
    (void)in_sizes; (void)n_in; (void)out_size;
    const float* x     = (const float*)d_in[0];
    const float* W_in  = (const float*)d_in[1];
    const float* cxw   = (const float*)d_in[2];
    const float* cxb   = (const float*)d_in[3];
    const float* czw   = (const float*)d_in[4];
    const float* czb   = (const float*)d_in[5];
    const float* Wxdbl = (const float*)d_in[6];
    const float* Wdt   = (const float*)d_in[7];
    const float* invdt = (const float*)d_in[8];
    const float* Dvec  = (const float*)d_in[9];
    const float* W_out = (const float*)d_in[10];
    const float* b_out = (const float*)d_in[11];
    float* out = (float*)d_out;

    cudaFuncSetAttribute(gemm_mma_kernel,
                         cudaFuncAttributeMaxDynamicSharedMemorySize, GSMEM);

    __nv_bfloat16 *xhi, *xlo, *chi, *clo, *binhi, *binlo, *bouthi, *boutlo;
    float *gxz = nullptr;
    cudaGetSymbolAddress((void**)&xhi, g_xhi);
    cudaGetSymbolAddress((void**)&xlo, g_xlo);
    cudaGetSymbolAddress((void**)&chi, g_chi);
    cudaGetSymbolAddress((void**)&clo, g_clo);
    cudaGetSymbolAddress((void**)&binhi, g_binhi);
    cudaGetSymbolAddress((void**)&binlo, g_binlo);
    cudaGetSymbolAddress((void**)&bouthi, g_bouthi);
    cudaGetSymbolAddress((void**)&boutlo, g_boutlo);
    cudaGetSymbolAddress((void**)&gxz, g_xz);

    // 1. split x into bf16 hi/lo; transpose+split W_in / W_out
    split_kernel<<<(MROWS * DMODEL) / 1024, 256>>>(x, xhi, xlo);
    tsplit_kernel<<<dim3(DINNER / 32, DMODEL / 32), 256>>>(W_in, binhi, binlo, DMODEL, DINNER);
    tsplit_kernel<<<dim3(DMODEL / 32, DINNER / 32), 256>>>(W_out, bouthi, boutlo, DINNER, DMODEL);
    // 2. xz = x @ W_in  (HMMA bf16x3)
    gemm_mma_kernel<<<dim3(DINNER / 128, MROWS / 128), 256, GSMEM>>>(
        xhi, xlo, binhi, binlo, gxz, nullptr, DINNER, DMODEL);
    // 3. depthwise conv + silu (xs -> g_xc fp32; z -> g_chi/g_clo bf16)
    conv_silu_kernel<<<dim3(DHALF / 256, SEQL / 8, BSZ), 256>>>(cxw, cxb, czw, czb);
    // 4. x_dbl = xs @ W_xdbl
    gemm_xdbl_kernel<<<MROWS / 32, 256>>>(Wxdbl);
    // 5. delta = softplus(dt_low @ W_dt + 2*inv_dt)
    gemm_dt_kernel<<<dim3(DHALF / 128, MROWS / 64), 256>>>(Wdt, invdt);
    // 6-8. chunked selective scan (y -> g_chi/g_clo bf16)
    scan_a_kernel<<<dim3(NCH, DHALF / 256, BSZ), 256>>>();
    scan_b_kernel<<<(BSZ * DHALF * DSTATE) / 256, 256>>>();
    scan_c_kernel<<<dim3(NCH, DHALF / 256, BSZ), 256>>>(Dvec);
    // 9. out = [y, z] @ W_out + b_out  (HMMA bf16x3)
    gemm_mma_kernel<<<dim3(DMODEL / 128, MROWS / 128), 256, GSMEM>>>(
        chi, clo, bouthi, boutlo, out, b_out, DMODEL, DINNER);
}

// round 16
// speedup vs baseline: 1.5111x; 1.3101x over previous
#include <cuda_runtime.h>
#include <cuda_bf16.h>
#include <cuda_fp16.h>
#include <math.h>
#include <stdint.h>

// ---------------- problem constants ----------------
#define BSZ     4
#define SEQL    2048
#define DMODEL  1024
#define DINNER  2048
#define DHALF   1024
#define DSTATE  16
#define DTRANK  64
#define MROWS   (BSZ * SEQL)            // 8192
#define XDBL_N  (DTRANK + 2 * DSTATE)   // 96
#define TC      64                      // scan chunk length
#define NCH     (SEQL / TC)             // 32 chunks

// ---------------- scratch (device globals; no allocation allowed) ----------------
__device__ __align__(16) float g_xz   [MROWS * DINNER];
__device__ __align__(16) float g_xc   [MROWS * DHALF];
__device__ __align__(16) float g_xdbl [MROWS * XDBL_N];
__device__ __align__(16) float g_delta[MROWS * DHALF];
__device__ __align__(16) float g_S    [BSZ * NCH * DHALF];
__device__ __align__(16) float g_H    [BSZ * NCH * DHALF * DSTATE];

// fp16 operands for tensor-core GEMMs (A split hi/lo exact; B single fp16)
__device__ __align__(16) __half g_xhi   [MROWS * DMODEL];
__device__ __align__(16) __half g_xlo   [MROWS * DMODEL];
__device__ __align__(16) __half g_chi   [MROWS * DINNER];   // [y | z] hi
__device__ __align__(16) __half g_clo   [MROWS * DINNER];   // [y | z] lo
__device__ __align__(16) __half g_binhi [DINNER * DMODEL];  // W_in^T  fp16
__device__ __align__(16) __half g_bouthi[DMODEL * DINNER];  // W_out^T fp16

// ---------------- PTX helpers (sm_80-class: cp.async / ldmatrix / mma.sync) ----------------
__device__ __forceinline__ uint32_t smem_u32(const void* p) {
    uint32_t a;
    asm("{ .reg .u64 t; cvta.to.shared.u64 t, %1; cvt.u32.u64 %0, t; }" : "=r"(a) : "l"(p));
    return a;
}
__device__ __forceinline__ void cp_async16(uint32_t dst, const void* src) {
    asm volatile("cp.async.cg.shared.global [%0], [%1], 16;" :: "r"(dst), "l"(src));
}
#define CP_COMMIT() asm volatile("cp.async.commit_group;" ::: "memory")
#define CP_WAIT1()  asm volatile("cp.async.wait_group 1;" ::: "memory")
#define CP_WAIT0()  asm volatile("cp.async.wait_group 0;" ::: "memory")

__device__ __forceinline__ void ldsm4(uint32_t (&r)[4], uint32_t addr) {
    asm volatile("ldmatrix.sync.aligned.m8n8.x4.shared.b16 {%0,%1,%2,%3}, [%4];"
        : "=r"(r[0]), "=r"(r[1]), "=r"(r[2]), "=r"(r[3]) : "r"(addr));
}
__device__ __forceinline__ void mma16816h(float (&c)[4], const uint32_t (&a)[4],
                                          uint32_t b0, uint32_t b1) {
    asm volatile("mma.sync.aligned.m16n8k16.row.col.f32.f16.f16.f32 "
        "{%0,%1,%2,%3}, {%4,%5,%6,%7}, {%8,%9}, {%0,%1,%2,%3};"
        : "+f"(c[0]), "+f"(c[1]), "+f"(c[2]), "+f"(c[3])
        : "r"(a[0]), "r"(a[1]), "r"(a[2]), "r"(a[3]), "r"(b0), "r"(b1));
}

// ---------------- operand prep: fp32 -> fp16 hi/lo split (A operands) ----------------
__global__ __launch_bounds__(256) void split_kernel(const float* __restrict__ src,
                                                    __half* __restrict__ hi,
                                                    __half* __restrict__ lo)
{
    const size_t i = ((size_t)blockIdx.x * 256 + threadIdx.x) * 4;
    float4 v = *(const float4*)(src + i);
    __half h0 = __float2half_rn(v.x);
    __half h1 = __float2half_rn(v.y);
    __half h2 = __float2half_rn(v.z);
    __half h3 = __float2half_rn(v.w);
    *(__half2*)(hi + i)     = __halves2half2(h0, h1);
    *(__half2*)(hi + i + 2) = __halves2half2(h2, h3);
    *(__half2*)(lo + i) =
        __halves2half2(__float2half_rn(v.x - __half2float(h0)),
                       __float2half_rn(v.y - __half2float(h1)));
    *(__half2*)(lo + i + 2) =
        __halves2half2(__float2half_rn(v.z - __half2float(h2)),
                       __float2half_rn(v.w - __half2float(h3)));
}

// ---------------- weight transpose: W[K][N] fp32 -> T[N][K] fp16 (single) ----------------
__global__ __launch_bounds__(256) void tsplit_kernel(const float* __restrict__ W,
                                                     __half* __restrict__ Thi,
                                                     int K, int N)
{
    __shared__ float t[32][33];
    const int n0 = blockIdx.x * 32, k0 = blockIdx.y * 32;
    const int tx = threadIdx.x & 31, ty = threadIdx.x >> 5;   // ty 0..7
#pragma unroll
    for (int j = 0; j < 4; j++)
        t[ty * 4 + j][tx] = W[(size_t)(k0 + ty * 4 + j) * N + n0 + tx];
    __syncthreads();
#pragma unroll
    for (int j = 0; j < 4; j++) {
        const int n = ty * 4 + j;
        Thi[(size_t)(n0 + n) * K + k0 + tx] = __float2half_rn(t[tx][n]);
    }
}

// ---------------- HMMA fp16 2-term GEMM: C[M,N] = (Ahi+Alo) * Bhi^T (+bias) ----------------
// CTA tile 128x128, 8 warps (warp tile 32x64), K-chunk 32 (two k16 halves),
// 2-stage cp.async ring (R11/R14-proven ordering):
//   wait -> sync -> LDSM(h0) -> MMA(h0) -> LDSM(h1) -> sync -> issue next -> MMA(h1)
#define GROWB   80                  // row stride bytes (64B data + 16B pad, conflict-free)
#define GTILE   (128 * GROWB)       // 10240
#define GSTAGE  (3 * GTILE)         // 30720 (Ahi | Alo | Bhi)
#define GSMEM   (2 * GSTAGE)        // 61440 bytes dynamic
#define GT_AHI  0
#define GT_ALO  GTILE
#define GT_BHI  (2 * GTILE)

__global__ __launch_bounds__(256, 2) void gemm_mma_kernel(
    const __half* __restrict__ Ahi, const __half* __restrict__ Alo,
    const __half* __restrict__ Bhi,
    float* __restrict__ C, const float* __restrict__ bias, int N, int K)
{
    extern __shared__ __align__(16) char smem[];
    const int tid  = threadIdx.x;
    const int lane = tid & 31;
    const int wid  = tid >> 5;
    const int bm = blockIdx.y * 128;
    const int bn = blockIdx.x * 128;
    const int wm = (wid & 3) * 32;
    const int wn = (wid >> 2) * 64;
    const int KT = K >> 5;                 // chunks of 32
    const uint32_t sbase = smem_u32(smem);

    const __half* gsrc[3] = { Ahi + (size_t)bm * K, Alo + (size_t)bm * K,
                              Bhi + (size_t)bn * K };

    // one stage: 3 tiles x 128 rows x 64 data bytes (stride 80)
    auto load_stage = [&](int s, int k0) {
#pragma unroll
        for (int t = 0; t < 6; t++) {
            const int linear = t * 256 + tid;      // 0..1535
            const int tile = linear >> 9;          // 0..2
            const int c    = linear & 511;
            const int row  = c >> 2;               // 0..127
            const int seg  = c & 3;                // 4 x 16B per row
            const uint32_t dst = sbase + s * GSTAGE + tile * GTILE + row * GROWB + seg * 16;
            cp_async16(dst, (const char*)gsrc[tile] + ((size_t)row * K + k0) * 2 + seg * 16);
        }
        CP_COMMIT();
    };

    float acc[2][8][4];
#pragma unroll
    for (int mi = 0; mi < 2; mi++)
#pragma unroll
        for (int ni = 0; ni < 8; ni++)
#pragma unroll
            for (int j = 0; j < 4; j++) acc[mi][ni][j] = 0.0f;

    load_stage(0, 0);
    if (KT > 1) load_stage(1, 32);

    uint32_t ah[2][4], al[2][4];
    uint32_t bh[8][2];

    auto ldsm_half = [&](uint32_t st, int half) {
        const uint32_t hoff = half * 32;           // k16 half -> +32B
#pragma unroll
        for (int mi = 0; mi < 2; mi++) {
            const int row = wm + mi * 16 + (lane & 15);
            const uint32_t off = row * GROWB + (lane >> 4) * 16 + hoff;
            ldsm4(ah[mi], st + GT_AHI + off);
            ldsm4(al[mi], st + GT_ALO + off);
        }
        const int grp = lane >> 3;
        const int roff = (grp >> 1) * 8 + (lane & 7);
        const int koff = (grp & 1) * 16 + hoff;
#pragma unroll
        for (int pi = 0; pi < 4; pi++) {
            const int nrow = wn + pi * 16 + roff;
            const uint32_t off = nrow * GROWB + koff;
            uint32_t r[4];
            ldsm4(r, st + GT_BHI + off);
            bh[pi * 2][0] = r[0]; bh[pi * 2][1] = r[1];
            bh[pi * 2 + 1][0] = r[2]; bh[pi * 2 + 1][1] = r[3];
        }
    };

    auto mma_all = [&]() {
#pragma unroll
        for (int mi = 0; mi < 2; mi++)
#pragma unroll
            for (int ni = 0; ni < 8; ni++) {
                mma16816h(acc[mi][ni], ah[mi], bh[ni][0], bh[ni][1]);
                mma16816h(acc[mi][ni], al[mi], bh[ni][0], bh[ni][1]);
            }
    };

    for (int kt = 0; kt < KT; kt++) {
        const int s = kt & 1;
        if (kt == KT - 1) CP_WAIT0(); else CP_WAIT1();
        __syncthreads();                            // stage s ready

        const uint32_t st = sbase + s * GSTAGE;
        ldsm_half(st, 0);
        mma_all();                                  // half 0
        ldsm_half(st, 1);
        __syncthreads();                            // all reads of stage s done
        if (kt + 2 < KT) load_stage(s, (kt + 2) * 32);   // overlaps half-1 MMAs
        mma_all();                                  // half 1
    }

    // epilogue: direct fp32 stores (+bias)
#pragma unroll
    for (int mi = 0; mi < 2; mi++)
#pragma unroll
        for (int ni = 0; ni < 8; ni++) {
            const int col = bn + wn + ni * 8 + (lane & 3) * 2;
            float b0 = 0.0f, b1 = 0.0f;
            if (bias) { b0 = bias[col]; b1 = bias[col + 1]; }
            const int r0 = bm + wm + mi * 16 + (lane >> 2);
            float2 v0 = { acc[mi][ni][0] + b0, acc[mi][ni][1] + b1 };
            float2 v1 = { acc[mi][ni][2] + b0, acc[mi][ni][3] + b1 };
            *(float2*)&C[(size_t)r0 * N + col] = v0;
            *(float2*)&C[(size_t)(r0 + 8) * N + col] = v1;
        }
}

// ---------------- depthwise conv (k=4, SAME: pad_lo=1) + silu ----------------
// xs-half -> g_xc (fp32); z-half -> g_chi/g_clo fp16 split directly.
__device__ __forceinline__ float silu_f(float v) {
    return __fdividef(v, 1.0f + __expf(-v));
}

__global__ __launch_bounds__(256) void conv_silu_kernel(
    const float* __restrict__ cwx, const float* __restrict__ cbx,
    const float* __restrict__ cwz, const float* __restrict__ cbz)
{
    const int c  = blockIdx.x * 256 + threadIdx.x;
    const int l0 = blockIdx.y * 8;
    const int b  = blockIdx.z;
    const float* base = g_xz + (size_t)b * SEQL * DINNER;

    const float wx0 = cwx[c], wx1 = cwx[DHALF + c], wx2 = cwx[2 * DHALF + c], wx3 = cwx[3 * DHALF + c];
    const float wz0 = cwz[c], wz1 = cwz[DHALF + c], wz2 = cwz[2 * DHALF + c], wz3 = cwz[3 * DHALF + c];
    const float bx = cbx[c], bz = cbz[c];

    float x0 = (l0 > 0) ? base[(size_t)(l0 - 1) * DINNER + c] : 0.0f;
    float x1 = base[(size_t)l0 * DINNER + c];
    float x2 = base[(size_t)(l0 + 1) * DINNER + c];
    float z0 = (l0 > 0) ? base[(size_t)(l0 - 1) * DINNER + DHALF + c] : 0.0f;
    float z1 = base[(size_t)l0 * DINNER + DHALF + c];
    float z2 = base[(size_t)(l0 + 1) * DINNER + DHALF + c];

#pragma unroll
    for (int t = 0; t < 8; t++) {
        const int l = l0 + t;
        const bool in = (l + 2 < SEQL);
        float x3 = in ? base[(size_t)(l + 2) * DINNER + c] : 0.0f;
        float z3 = in ? base[(size_t)(l + 2) * DINNER + DHALF + c] : 0.0f;
        float vx = fmaf(x0, wx0, fmaf(x1, wx1, fmaf(x2, wx2, fmaf(x3, wx3, bx))));
        float vz = fmaf(z0, wz0, fmaf(z1, wz1, fmaf(z2, wz2, fmaf(z3, wz3, bz))));
        g_xc[((size_t)b * SEQL + l) * DHALF + c] = silu_f(vx);
        const float sz = silu_f(vz);
        const __half h = __float2half_rn(sz);
        const size_t zi = ((size_t)b * SEQL + l) * DINNER + DHALF + c;
        g_chi[zi] = h;
        g_clo[zi] = __float2half_rn(sz - __half2float(h));
        x0 = x1; x1 = x2; x2 = x3;
        z0 = z1; z1 = z2; z2 = z3;
    }
}

// ---------------- x_dbl = xs_conv @ W_xdbl (M=8192, K=1024, N=96) ----------------
__global__ __launch_bounds__(256) void gemm_xdbl_kernel(const float* __restrict__ Wx)
{
    __shared__ float As[32][32];
    __shared__ float Bs[32][96];
    const int tid = threadIdx.x;
    const int m0  = blockIdx.x * 32;
    const int tx  = tid & 7;
    const int ty  = tid >> 3;

    float acc[12];
#pragma unroll
    for (int j = 0; j < 12; j++) acc[j] = 0.0f;

    for (int k0 = 0; k0 < DHALF; k0 += 32) {
        {
            const int row = tid >> 3, c4 = tid & 7;
            *(float4*)&As[row][c4 * 4] =
                *(const float4*)&g_xc[(size_t)(m0 + row) * DHALF + k0 + c4 * 4];
        }
#pragma unroll
        for (int i = 0; i < 3; i++) {
            const int idx = i * 256 + tid;
            if (idx < 768) {
                const int row = idx / 24, c4 = idx % 24;
                *(float4*)&Bs[row][c4 * 4] =
                    *(const float4*)&Wx[(size_t)(k0 + row) * XDBL_N + c4 * 4];
            }
        }
        __syncthreads();
#pragma unroll
        for (int kk = 0; kk < 32; kk++) {
            const float a = As[ty][kk];
            float4 b0 = *(const float4*)&Bs[kk][tx * 12];
            float4 b1 = *(const float4*)&Bs[kk][tx * 12 + 4];
            float4 b2 = *(const float4*)&Bs[kk][tx * 12 + 8];
            acc[0]  = fmaf(a, b0.x, acc[0]);  acc[1]  = fmaf(a, b0.y, acc[1]);
            acc[2]  = fmaf(a, b0.z, acc[2]);  acc[3]  = fmaf(a, b0.w, acc[3]);
            acc[4]  = fmaf(a, b1.x, acc[4]);  acc[5]  = fmaf(a, b1.y, acc[5]);
            acc[6]  = fmaf(a, b1.z, acc[6]);  acc[7]  = fmaf(a, b1.w, acc[7]);
            acc[8]  = fmaf(a, b2.x, acc[8]);  acc[9]  = fmaf(a, b2.y, acc[9]);
            acc[10] = fmaf(a, b2.z, acc[10]); acc[11] = fmaf(a, b2.w, acc[11]);
        }
        __syncthreads();
    }
#pragma unroll
    for (int j = 0; j < 12; j++)
        g_xdbl[(size_t)(m0 + ty) * XDBL_N + tx * 12 + j] = acc[j];
}

// ---------------- delta = softplus(dt_low @ W_dt + 2*inv_dt)  (M=8192, K=64, N=1024) ----------------
__global__ __launch_bounds__(256) void gemm_dt_kernel(const float* __restrict__ Wdt,
                                                      const float* __restrict__ inv_dt)
{
    __shared__ float As[64][64];
    __shared__ float Bs[64][128];
    const int tid = threadIdx.x;
    const int n0  = blockIdx.x * 128;
    const int m0  = blockIdx.y * 64;

#pragma unroll
    for (int i = 0; i < 4; i++) {
        const int idx = i * 256 + tid;
        const int row = idx >> 4, c4 = idx & 15;
        *(float4*)&As[row][c4 * 4] =
            *(const float4*)&g_xdbl[(size_t)(m0 + row) * XDBL_N + c4 * 4];
    }
#pragma unroll
    for (int i = 0; i < 8; i++) {
        const int idx = i * 256 + tid;
        const int row = idx >> 5, c4 = idx & 31;
        *(float4*)&Bs[row][c4 * 4] =
            *(const float4*)&Wdt[(size_t)row * DHALF + n0 + c4 * 4];
    }
    __syncthreads();

    const int ty = tid >> 5;
    const int tx = tid & 31;
    float acc[8][4];
#pragma unroll
    for (int i = 0; i < 8; i++)
#pragma unroll
        for (int j = 0; j < 4; j++) acc[i][j] = 0.0f;

#pragma unroll 8
    for (int k = 0; k < 64; k++) {
        float4 b = *(const float4*)&Bs[k][tx * 4];
#pragma unroll
        for (int i = 0; i < 8; i++) {
            const float a = As[ty * 8 + i][k];
            acc[i][0] = fmaf(a, b.x, acc[i][0]);
            acc[i][1] = fmaf(a, b.y, acc[i][1]);
            acc[i][2] = fmaf(a, b.z, acc[i][2]);
            acc[i][3] = fmaf(a, b.w, acc[i][3]);
        }
    }

    float iv[4];
#pragma unroll
    for (int j = 0; j < 4; j++) iv[j] = 2.0f * inv_dt[n0 + tx * 4 + j];
#pragma unroll
    for (int i = 0; i < 8; i++) {
        float d[4];
#pragma unroll
        for (int j = 0; j < 4; j++) {
            float xv = acc[i][j] + iv[j];
            d[j] = (xv > 15.0f) ? xv : log1pf(__expf(xv));
        }
        float4 o = {d[0], d[1], d[2], d[3]};
        *(float4*)&g_delta[(size_t)(m0 + ty * 8 + i) * DHALF + n0 + tx * 4] = o;
    }
}

// ---------------- scan phase A: per-chunk local end-state H and sum-of-delta S ----------------
__global__ __launch_bounds__(256) void scan_a_kernel()
{
    __shared__ float Bsm[TC][DSTATE];
    const int b  = blockIdx.z;
    const int dc = blockIdx.y;
    const int ch = blockIdx.x;
    const int tid = threadIdx.x;
    const int d  = dc * 256 + tid;
    const int m0 = b * SEQL + ch * TC;

#pragma unroll
    for (int i = 0; i < 4; i++) {
        const int idx = i * 256 + tid;
        const int t = idx >> 4, n = idx & 15;
        Bsm[t][n] = g_xdbl[(size_t)(m0 + t) * XDBL_N + DTRANK + n];
    }
    __syncthreads();

    float h[DSTATE];
#pragma unroll
    for (int n = 0; n < DSTATE; n++) h[n] = 0.0f;
    float S = 0.0f;

    for (int t = 0; t < TC; t++) {
        const float delta = g_delta[(size_t)(m0 + t) * DHALF + d];
        const float u     = g_xc  [(size_t)(m0 + t) * DHALF + d];
        const float e  = __expf(-delta);
        const float du = delta * u;
        S += delta;
        float en = e;
#pragma unroll
        for (int n = 0; n < DSTATE; n++) {
            h[n] = fmaf(en, h[n], du * Bsm[t][n]);
            en *= e;
        }
    }
    const int cidx = (b * NCH + ch) * DHALF + d;
    g_S[cidx] = S;
    float* Hp = &g_H[(size_t)cidx * DSTATE];
#pragma unroll
    for (int q = 0; q < 4; q++) {
        float4 o = {h[q * 4], h[q * 4 + 1], h[q * 4 + 2], h[q * 4 + 3]};
        *(float4*)&Hp[q * 4] = o;
    }
}

// ---------------- scan phase B: stitch chunk boundaries ----------------
__global__ __launch_bounds__(256) void scan_b_kernel()
{
    const int g = blockIdx.x * 256 + threadIdx.x;
    const int n = g & 15;
    const int d = (g >> 4) & (DHALF - 1);
    const int b = g >> 14;
    const float nn = -(float)(n + 1);

    float hin = 0.0f;
    for (int c = 0; c < NCH; c++) {
        const int cidx = (b * NCH + c) * DHALF + d;
        const float S  = g_S[cidx];
        const float Hc = g_H[(size_t)cidx * DSTATE + n];
        const float P  = __expf(nn * S);
        const float nxt = fmaf(P, hin, Hc);
        g_H[(size_t)cidx * DSTATE + n] = hin;
        hin = nxt;
    }
}

// ---------------- scan phase C: exact recurrence; emit y as fp16 hi/lo ----------------
__global__ __launch_bounds__(256) void scan_c_kernel(const float* __restrict__ Dvec)
{
    __shared__ float Bsm[TC][DSTATE];
    __shared__ float Csm[TC][DSTATE];
    const int b  = blockIdx.z;
    const int dc = blockIdx.y;
    const int ch = blockIdx.x;
    const int tid = threadIdx.x;
    const int d  = dc * 256 + tid;
    const int m0 = b * SEQL + ch * TC;

#pragma unroll
    for (int i = 0; i < 8; i++) {
        const int idx = i * 256 + tid;
        const int t = idx >> 5, q = idx & 31;
        const float v = g_xdbl[(size_t)(m0 + t) * XDBL_N + DTRANK + q];
        if (q < 16) Bsm[t][q] = v;
        else        Csm[t][q - 16] = v;
    }

    const int cidx = (b * NCH + ch) * DHALF + d;
    const float* Hp = &g_H[(size_t)cidx * DSTATE];
    float h[DSTATE];
#pragma unroll
    for (int q = 0; q < 4; q++) {
        float4 v = *(const float4*)&Hp[q * 4];
        h[q * 4] = v.x; h[q * 4 + 1] = v.y; h[q * 4 + 2] = v.z; h[q * 4 + 3] = v.w;
    }
    const float Dv = Dvec[d];
    __syncthreads();

    for (int t = 0; t < TC; t++) {
        const float delta = g_delta[(size_t)(m0 + t) * DHALF + d];
        const float u     = g_xc  [(size_t)(m0 + t) * DHALF + d];
        const float e  = __expf(-delta);
        const float du = delta * u;
        float en = e;
        float y = 0.0f;
#pragma unroll
        for (int n = 0; n < DSTATE; n++) {
            h[n] = fmaf(en, h[n], du * Bsm[t][n]);
            y = fmaf(h[n], Csm[t][n], y);
            en *= e;
        }
        const float yv = fmaf(u, Dv, y);
        const __half hh = __float2half_rn(yv);
        const size_t yi = (size_t)(m0 + t) * DINNER + d;
        g_chi[yi] = hh;
        g_clo[yi] = __float2half_rn(yv - __half2float(hh));
    }
}

// ---------------- launcher ----------------
extern "C" void kernel_launch(void* const* d_in, const int* in_sizes, int n_in,
                              void* d_out, int out_size)
{
    (void)in_sizes; (void)n_in; (void)out_size;
    const float* x     = (const float*)d_in[0];
    const float* W_in  = (const float*)d_in[1];
    const float* cxw   = (const float*)d_in[2];
    const float* cxb   = (const float*)d_in[3];
    const float* czw   = (const float*)d_in[4];
    const float* czb   = (const float*)d_in[5];
    const float* Wxdbl = (const float*)d_in[6];
    const float* Wdt   = (const float*)d_in[7];
    const float* invdt = (const float*)d_in[8];
    const float* Dvec  = (const float*)d_in[9];
    const float* W_out = (const float*)d_in[10];
    const float* b_out = (const float*)d_in[11];
    float* out = (float*)d_out;

    cudaFuncSetAttribute(gemm_mma_kernel,
                         cudaFuncAttributeMaxDynamicSharedMemorySize, GSMEM);

    __half *xhi, *xlo, *chi, *clo, *binhi, *bouthi;
    float *gxz = nullptr;
    cudaGetSymbolAddress((void**)&xhi, g_xhi);
    cudaGetSymbolAddress((void**)&xlo, g_xlo);
    cudaGetSymbolAddress((void**)&chi, g_chi);
    cudaGetSymbolAddress((void**)&clo, g_clo);
    cudaGetSymbolAddress((void**)&binhi, g_binhi);
    cudaGetSymbolAddress((void**)&bouthi, g_bouthi);
    cudaGetSymbolAddress((void**)&gxz, g_xz);

    // 1. split x into fp16 hi/lo; transpose W_in / W_out to fp16
    split_kernel<<<(MROWS * DMODEL) / 1024, 256>>>(x, xhi, xlo);
    tsplit_kernel<<<dim3(DINNER / 32, DMODEL / 32), 256>>>(W_in, binhi, DMODEL, DINNER);
    tsplit_kernel<<<dim3(DMODEL / 32, DINNER / 32), 256>>>(W_out, bouthi, DINNER, DMODEL);
    // 2. xz = x @ W_in  (HMMA fp16 2-term)
    gemm_mma_kernel<<<dim3(DINNER / 128, MROWS / 128), 256, GSMEM>>>(
        xhi, xlo, binhi, gxz, nullptr, DINNER, DMODEL);
    // 3. depthwise conv + silu (xs -> g_xc fp32; z -> g_chi/g_clo fp16)
    conv_silu_kernel<<<dim3(DHALF / 256, SEQL / 8, BSZ), 256>>>(cxw, cxb, czw, czb);
    // 4. x_dbl = xs @ W_xdbl
    gemm_xdbl_kernel<<<MROWS / 32, 256>>>(Wxdbl);
    // 5. delta = softplus(dt_low @ W_dt + 2*inv_dt)
    gemm_dt_kernel<<<dim3(DHALF / 128, MROWS / 64), 256>>>(Wdt, invdt);
    // 6-8. chunked selective scan (y -> g_chi/g_clo fp16)
    scan_a_kernel<<<dim3(NCH, DHALF / 256, BSZ), 256>>>();
    scan_b_kernel<<<(BSZ * DHALF * DSTATE) / 256, 256>>>();
    scan_c_kernel<<<dim3(NCH, DHALF / 256, BSZ), 256>>>(Dvec);
    // 9. out = [y, z] @ W_out + b_out  (HMMA fp16 2-term)
    gemm_mma_kernel<<<dim3(DMODEL / 128, MROWS / 128), 256, GSMEM>>>(
        chi, clo, bouthi, out, b_out, DMODEL, DINNER);
}